// round 3
// baseline (speedup 1.0000x reference)
#include <cuda_runtime.h>
#include <cstdint>

// Problem constants (fixed by the reference):
//   T=4 tables, E=1,000,000 rows/table, D=128 dim, B=8192 bags, L=32 per bag
// Inputs (identified by element count at runtime — order-agnostic):
//   indices: int32  [T, B, L]   -> T*B*L = 1,048,576 elements
//            (JAX w/o x64 downcasts int64 -> int32; harness only supports i32)
//   weights: float32 [T, E, D]  -> T*E*D = 512,000,000 elements
// Output: float32 [B, T*D], out[b][t*D + d]

namespace {
constexpr int T = 4;
constexpr long long E = 1000000;
constexpr int D = 128;
constexpr int B = 8192;
constexpr int L = 32;
constexpr int D4 = D / 4;           // 32 float4 per row -> one per lane
constexpr int WARPS_PER_BLOCK = 8;
constexpr int THREADS = WARPS_PER_BLOCK * 32;
constexpr int NUM_BAGS = T * B;     // 32768 warps total
constexpr long long IDX_ELEMS = (long long)T * B * L;   // 1,048,576
}

__global__ __launch_bounds__(THREADS)
void embedding_bag_sum_kernel(const int* __restrict__ indices,
                              const float4* __restrict__ weights,
                              float4* __restrict__ out)
{
    const int warp_in_block = threadIdx.x >> 5;
    const int lane = threadIdx.x & 31;
    const int bag = blockIdx.x * WARPS_PER_BLOCK + warp_in_block;

    // indices layout [T, B, L]: bag id == t*B + b, contiguous L per bag.
    const int t = bag >> 13;          // bag / B, B = 8192
    const int b = bag & (B - 1);

    // Each lane holds one of the 32 bag indices; broadcast via shfl.
    const int my_idx = __ldg(indices + (size_t)bag * L + lane);

    const float4* wt = weights + (size_t)t * (size_t)E * D4;

    float4 acc = make_float4(0.f, 0.f, 0.f, 0.f);

    #pragma unroll
    for (int j = 0; j < L; ++j) {
        const int row = __shfl_sync(0xffffffffu, my_idx, j);
        const float4 v = __ldg(wt + (size_t)row * D4 + lane);
        acc.x += v.x;
        acc.y += v.y;
        acc.z += v.z;
        acc.w += v.w;
    }

    // out[b][t*D + d]; lane covers d = lane*4 .. lane*4+3
    out[((size_t)b * T + t) * D4 + lane] = acc;
}

extern "C" void kernel_launch(void* const* d_in, const int* in_sizes, int n_in,
                              void* d_out, int out_size)
{
    // Identify inputs by element count (order-agnostic).
    const int*    indices = nullptr;
    const float4* weights = nullptr;
    for (int i = 0; i < n_in; ++i) {
        if ((long long)in_sizes[i] == IDX_ELEMS)
            indices = (const int*)d_in[i];
        else
            weights = (const float4*)d_in[i];
    }
    float4* out = (float4*)d_out;

    const int blocks = NUM_BAGS / WARPS_PER_BLOCK;  // 4096 blocks
    embedding_bag_sum_kernel<<<blocks, THREADS>>>(indices, weights, out);
}